// round 7
// baseline (speedup 1.0000x reference)
#include <cuda_runtime.h>
#include <math.h>

#define NPLANETS      10
#define NEDGES_LOC    45
#define NT_PER_BLOCK  8
#define EDGES_PB      360
#define THREADS       384
#define HID           32
#define BSTRIDE       33

__device__ float gBfrag[4096];   // tf32-split W2 fragments: hi[0..2047], lo[2048..4095]

__device__ __forceinline__ float tanha(float x) {
    float y; asm("tanh.approx.f32 %0, %1;" : "=f"(y) : "f"(x));
    return y;
}
__device__ __forceinline__ void mma8(float* d, const unsigned* a, unsigned b0, unsigned b1) {
    asm volatile("mma.sync.aligned.m16n8k8.row.col.f32.tf32.tf32.f32 "
        "{%0,%1,%2,%3}, {%4,%5,%6,%7}, {%8,%9}, {%0,%1,%2,%3};"
        : "+f"(d[0]), "+f"(d[1]), "+f"(d[2]), "+f"(d[3])
        : "r"(a[0]), "r"(a[1]), "r"(a[2]), "r"(a[3]), "r"(b0), "r"(b1));
}

// Prologue: split W2 into tf32 hi/lo fragment tables.
// Fragment (ki,ni,lane,reg): b_reg holds B[k=8ki+tig+4reg][n=8ni+g], g=lane>>2, tig=lane&3.
__global__ void prep_bfrag(const float* __restrict__ W2) {
    int idx = blockIdx.x * blockDim.x + threadIdx.x;   // 0..2047
    if (idx >= 2048) return;
    int reg  = idx & 1;
    int lane = (idx >> 1) & 31;
    int ni   = (idx >> 6) & 3;
    int ki   = (idx >> 8) & 3;
    int tig = lane & 3, g = lane >> 2;
    int k = ki * 8 + tig + reg * 4;
    int n = ni * 8 + g;
    float w = W2[k * 32 + n];
    unsigned uh = __float_as_uint(w) & 0xFFFFE000u;    // tf32 truncation (valid tf32 pattern)
    float lo = w - __uint_as_float(uh);                // exact residual
    unsigned ul = __float_as_uint(lo) & 0xFFFFE000u;
    gBfrag[idx]        = __uint_as_float(uh);
    gBfrag[2048 + idx] = __uint_as_float(ul);
}

__global__ void __launch_bounds__(THREADS, 2)
learnforces_kernel(const float* __restrict__ D_V,
                   const float* __restrict__ logm,
                   const float* __restrict__ W1,
                   const float* __restrict__ b1,
                   const float* __restrict__ W2,
                   const float* __restrict__ b2,
                   const float* __restrict__ W3,
                   const float* __restrict__ b3,
                   const int*   __restrict__ senders,
                   const int*   __restrict__ receivers,
                   float*       __restrict__ out,
                   int ntime)
{
    __shared__ __align__(16) float sB[4096];              // W2 fragments hi|lo
    __shared__ __align__(16) float sW1[3 * HID];
    __shared__ __align__(16) float sW3p[HID * 4];          // [w0,w1,w2,0] per row
    __shared__ float sb2[HID];
    __shared__ float sb3[4];
    __shared__ float sbias1[NEDGES_LOC * BSTRIDE];
    __shared__ float s_lm[NPLANETS];
    __shared__ float s_invm[NPLANETS];
    __shared__ int   s_snd[NEDGES_LOC];
    __shared__ int   s_rcv[NEDGES_LOC];
    __shared__ int   s_glist[NPLANETS][9];
    __shared__ __align__(16) float4 s_e[EDGES_PB];

    const int tid  = threadIdx.x;
    const int lane = tid & 31;
    const int warp = tid >> 5;
    const int g    = lane >> 2;
    const int tig  = lane & 3;

    // ---- cooperative setup ----
    {
        const float4* src = (const float4*)gBfrag;
        float4* dst = (float4*)sB;
        for (int i = tid; i < 1024; i += THREADS) dst[i] = src[i];
    }
    for (int i = tid; i < 3 * HID; i += THREADS) sW1[i] = W1[i];
    if (tid < HID) {
        sb2[tid] = b2[tid];
        sW3p[tid * 4 + 0] = W3[tid * 3 + 0];
        sW3p[tid * 4 + 1] = W3[tid * 3 + 1];
        sW3p[tid * 4 + 2] = W3[tid * 3 + 2];
        sW3p[tid * 4 + 3] = 0.0f;
    }
    if (tid < 4) sb3[tid] = (tid < 3) ? b3[tid] : 0.0f;
    if (tid < NEDGES_LOC) { s_snd[tid] = senders[tid]; s_rcv[tid] = receivers[tid]; }
    if (tid < NPLANETS) {
        float v = fminf(fmaxf(logm[tid], -12.0f), 12.0f);
        s_lm[tid]   = v;
        s_invm[tid] = expf(-v);
    }
    __syncthreads();

    if (tid < NPLANETS) {
        int cnt = 0;
        for (int le = 0; le < NEDGES_LOC; le++) {
            if (s_rcv[le] == tid) s_glist[tid][cnt++] =  (le + 1);
            else if (s_snd[le] == tid) s_glist[tid][cnt++] = -(le + 1);
        }
    }
    for (int i = tid; i < NEDGES_LOC * HID; i += THREADS) {
        int le = i >> 5;
        int j  = i & 31;
        sbias1[le * BSTRIDE + j] = b1[j] + s_lm[s_rcv[le]] * W1[3 * HID + j]
                                         + s_lm[s_snd[le]] * W1[4 * HID + j];
    }
    __syncthreads();

    // ---- cart->sph for own edge (warp-local edge index == lane; block edge == tid) ----
    {
        long blkbase = (long)blockIdx.x * EDGES_PB;
        int  eloc = (tid < EDGES_PB) ? tid : (EDGES_PB - 1);   // clamp invalid lanes
        long ge = blkbase + eloc;
        float x = D_V[ge * 3 + 0];
        float y = D_V[ge * 3 + 1];
        float z = D_V[ge * 3 + 2];
        float r2 = fmaf(x, x, fmaf(y, y, z * z));
        float r  = sqrtf(r2);
        float ct = fminf(fmaxf(__fdividef(z, r), -1.0f), 1.0f);
        float th = acosf(ct);
        float ph = atan2f(y, x);

        // distribute coords of my 4 fragment rows {g, g+8, g+16, g+24}
        float rr[4], tt[4], pp[4];
        int   le[4];
#pragma unroll
        for (int m = 0; m < 4; m++) {
            int src = g + 8 * m;
            rr[m] = __shfl_sync(0xFFFFFFFFu, r,  src);
            tt[m] = __shfl_sync(0xFFFFFFFFu, th, src);
            pp[m] = __shfl_sync(0xFFFFFFFFu, ph, src);
            int e = warp * 32 + g + 8 * m;                     // block-local edge (<=383)
            le[m] = e % NEDGES_LOC;
        }

        // ---- layer1 in A-fragment layout + 3xTF32 MMA for layer2 ----
        float D[2][4][4];
#pragma unroll
        for (int mi = 0; mi < 2; mi++)
#pragma unroll
            for (int ni = 0; ni < 4; ni++)
#pragma unroll
                for (int c = 0; c < 4; c++) D[mi][ni][c] = 0.0f;

#pragma unroll
        for (int ki = 0; ki < 4; ki++) {
            unsigned Ahi[2][4], Alo[2][4];
#pragma unroll
            for (int half = 0; half < 2; half++) {
                int c = 8 * ki + tig + 4 * half;
                float w0 = sW1[c], w1 = sW1[32 + c], w2 = sW1[64 + c];
#pragma unroll
                for (int mi = 0; mi < 2; mi++) {
#pragma unroll
                    for (int rh = 0; rh < 2; rh++) {
                        int m = 2 * mi + rh;                   // row = g + 8m
                        float pre = fmaf(rr[m], w0,
                                    fmaf(tt[m], w1,
                                    fmaf(pp[m], w2, sbias1[le[m] * BSTRIDE + c])));
                        float h  = tanha(pre);
                        unsigned uh = __float_as_uint(h) & 0xFFFFE000u;
                        float    lo = h - __uint_as_float(uh);
                        unsigned ul = __float_as_uint(lo) & 0xFFFFE000u;
                        Ahi[mi][half * 2 + rh] = uh;           // a0,a1 = cols tig; a2,a3 = tig+4
                        Alo[mi][half * 2 + rh] = ul;
                    }
                }
            }
#pragma unroll
            for (int ni = 0; ni < 4; ni++) {
                int pos = ki * 4 + ni;
                float2 bh = *(const float2*)&sB[(pos * 32 + lane) * 2];
                float2 bl = *(const float2*)&sB[2048 + (pos * 32 + lane) * 2];
                unsigned bh0 = __float_as_uint(bh.x), bh1 = __float_as_uint(bh.y);
                unsigned bl0 = __float_as_uint(bl.x), bl1 = __float_as_uint(bl.y);
#pragma unroll
                for (int mi = 0; mi < 2; mi++) {
                    mma8(D[mi][ni], Ahi[mi], bh0, bh1);
                    mma8(D[mi][ni], Alo[mi], bh0, bh1);
                    mma8(D[mi][ni], Ahi[mi], bl0, bl1);
                }
            }
        }

        // ---- epilogue: +b2, tanh, @W3, butterfly reduce over tig ----
        float ex[4], ey[4], ez[4];
#pragma unroll
        for (int m = 0; m < 4; m++) { ex[m] = 0.0f; ey[m] = 0.0f; ez[m] = 0.0f; }
#pragma unroll
        for (int ni = 0; ni < 4; ni++) {
            int j0 = 8 * ni + 2 * tig;
            float4 wa = *(const float4*)&sW3p[j0 * 4];
            float4 wb = *(const float4*)&sW3p[(j0 + 1) * 4];
            float bb0 = sb2[j0], bb1 = sb2[j0 + 1];
#pragma unroll
            for (int mi = 0; mi < 2; mi++) {
                float h0 = tanha(D[mi][ni][0] + bb0);   // row g+16mi,   col j0
                float h1 = tanha(D[mi][ni][1] + bb1);   // row g+16mi,   col j0+1
                float h2 = tanha(D[mi][ni][2] + bb0);   // row g+8+16mi, col j0
                float h3 = tanha(D[mi][ni][3] + bb1);   // row g+8+16mi, col j0+1
                int mA = 2 * mi, mB = 2 * mi + 1;
                ex[mA] = fmaf(h0, wa.x, fmaf(h1, wb.x, ex[mA]));
                ey[mA] = fmaf(h0, wa.y, fmaf(h1, wb.y, ey[mA]));
                ez[mA] = fmaf(h0, wa.z, fmaf(h1, wb.z, ez[mA]));
                ex[mB] = fmaf(h2, wa.x, fmaf(h3, wb.x, ex[mB]));
                ey[mB] = fmaf(h2, wa.y, fmaf(h3, wb.y, ey[mB]));
                ez[mB] = fmaf(h2, wa.z, fmaf(h3, wb.z, ez[mB]));
            }
        }
#pragma unroll
        for (int m = 0; m < 4; m++) {
            ex[m] += __shfl_xor_sync(0xFFFFFFFFu, ex[m], 1);
            ex[m] += __shfl_xor_sync(0xFFFFFFFFu, ex[m], 2);
            ey[m] += __shfl_xor_sync(0xFFFFFFFFu, ey[m], 1);
            ey[m] += __shfl_xor_sync(0xFFFFFFFFu, ey[m], 2);
            ez[m] += __shfl_xor_sync(0xFFFFFFFFu, ez[m], 1);
            ez[m] += __shfl_xor_sync(0xFFFFFFFFu, ez[m], 2);
        }

        // redistribute: lane L owns row L = (L&7) + 8*(L>>3); src group = (L&7)*4
        float fe0 = 0.0f, fe1 = 0.0f, fe2 = 0.0f;
        int srcl = (lane & 7) * 4;
        int mw   = lane >> 3;
#pragma unroll
        for (int m = 0; m < 4; m++) {
            float tx = __shfl_sync(0xFFFFFFFFu, ex[m], srcl);
            float ty = __shfl_sync(0xFFFFFFFFu, ey[m], srcl);
            float tz = __shfl_sync(0xFFFFFFFFu, ez[m], srcl);
            if (mw == m) { fe0 = tx; fe1 = ty; fe2 = tz; }
        }
        fe0 += sb3[0]; fe1 += sb3[1]; fe2 += sb3[2];

        // sph -> cart, store per-edge force
        float st, ctq, sp, cp;
        __sincosf(fe1, &st, &ctq);
        __sincosf(fe2, &sp, &cp);
        float rs = fe0 * st;
        if (tid < EDGES_PB)
            s_e[tid] = make_float4(rs * cp, rs * sp, fe0 * ctq, 0.0f);
    }
    __syncthreads();

    // ---- gather-based scatter: 240 threads = 8 t * 10 planets * 3 comps ----
    if (tid < NT_PER_BLOCK * NPLANETS * 3) {
        int tl  = tid / (NPLANETS * 3);
        int rem = tid - tl * (NPLANETS * 3);
        int p   = rem / 3;
        int c   = rem - p * 3;
        long t  = (long)blockIdx.x * NT_PER_BLOCK + tl;
        if (t < (long)ntime) {
            const float* eb = (const float*)(s_e + tl * NEDGES_LOC);
            float sum = 0.0f;
#pragma unroll
            for (int k = 0; k < 9; k++) {
                int gidx = s_glist[p][k];
                int lle  = (gidx > 0 ? gidx : -gidx) - 1;
                float v  = eb[lle * 4 + c];
                sum += (gidx > 0) ? v : -v;
            }
            out[t * (NPLANETS * 3) + rem] = sum * s_invm[p];
        }
    }
}

extern "C" void kernel_launch(void* const* d_in, const int* in_sizes, int n_in,
                              void* d_out, int out_size)
{
    const float* D_V       = (const float*)d_in[0];
    const float* logm      = (const float*)d_in[1];
    const float* W1        = (const float*)d_in[2];
    const float* b1        = (const float*)d_in[3];
    const float* W2        = (const float*)d_in[4];
    const float* b2        = (const float*)d_in[5];
    const float* W3        = (const float*)d_in[6];
    const float* b3        = (const float*)d_in[7];
    const int*   senders   = (const int*)d_in[8];
    const int*   receivers = (const int*)d_in[9];
    float*       out       = (float*)d_out;

    int nedges = in_sizes[8];                  // 45
    int ntime  = in_sizes[0] / (3 * nedges);   // 100000

    prep_bfrag<<<2, 1024>>>(W2);

    int grid = (ntime + NT_PER_BLOCK - 1) / NT_PER_BLOCK;
    learnforces_kernel<<<grid, THREADS>>>(D_V, logm, W1, b1, W2, b2, W3, b3,
                                          senders, receivers, out, ntime);
}

// round 8
// speedup vs baseline: 1.6102x; 1.6102x over previous
#include <cuda_runtime.h>
#include <math.h>

#define NPLANETS      10
#define NEDGES_LOC    45
#define NT_PER_BLOCK  7
#define EDGES_PB      (NEDGES_LOC * NT_PER_BLOCK)   // 315
#define THREADS       320
#define HID           32
#define BSTRIDE       33

typedef unsigned long long ull;

// Weights in constant memory. W2/b2 stored as pre-packed 64-bit float pairs:
// LDCU.128 yields ready-to-use fma.rn.f32x2 operands with zero pack movs.
__constant__ float      cW1[3 * HID];
__constant__ ulonglong2 cW2p[HID * HID / 4];   // 256 x (4 floats)
__constant__ ulonglong2 cb2p[HID / 4];
__constant__ float      cW3[HID * 3];
__constant__ float      cb3[3];

__device__ __forceinline__ float tanha(float x) {
    float y; asm("tanh.approx.f32 %0, %1;" : "=f"(y) : "f"(x));
    return y;
}
__device__ __forceinline__ ull pk2(float x) {
    ull d; unsigned u = __float_as_uint(x);
    asm("mov.b64 %0, {%1, %1};" : "=l"(d) : "r"(u));
    return d;
}
__device__ __forceinline__ ull fma2(ull a, ull b, ull c) {
    ull d; asm("fma.rn.f32x2 %0, %1, %2, %3;" : "=l"(d) : "l"(a), "l"(b), "l"(c));
    return d;
}
__device__ __forceinline__ void upk(ull v, float& lo, float& hi) {
    unsigned a, b;
    asm("mov.b64 {%0, %1}, %2;" : "=r"(a), "=r"(b) : "l"(v));
    lo = __uint_as_float(a); hi = __uint_as_float(b);
}

// acos via A&S 4.4.45 (abs err <= 6.7e-5 rad): sqrt(1-|x|)*poly, reflected.
__device__ __forceinline__ float acos_f(float x) {
    float ax = fabsf(x);
    float sq = sqrtf(1.0f - ax);
    float p  = fmaf(ax, fmaf(ax, fmaf(ax, -0.0187293f, 0.0742610f),
                             -0.2121144f), 1.5707288f);
    float th = sq * p;
    return (x < 0.0f) ? (3.14159274f - th) : th;
}

// atan2 via degree-11 minimax on [0,1] + quadrant fixup (err ~1e-5 rad).
__device__ __forceinline__ float atan2_f(float y, float x) {
    float ax = fabsf(x), ay = fabsf(y);
    float mn = fminf(ax, ay), mx = fmaxf(ax, ay);
    float a  = __fdividef(mn, mx);
    float s  = a * a;
    float t  = fmaf(s, fmaf(s, fmaf(s, fmaf(s, fmaf(s, -0.01172120f, 0.05265332f),
                    -0.11643287f), 0.19354346f), -0.33262347f), 0.99997726f) * a;
    if (ay > ax)   t = 1.57079637f - t;
    if (x < 0.0f)  t = 3.14159274f - t;
    return copysignf(t, y);
}

__global__ void __launch_bounds__(THREADS, 4)
learnforces_kernel(const float* __restrict__ D_V,
                   const float* __restrict__ logm,
                   const float* __restrict__ W1,
                   const float* __restrict__ b1,
                   const int*   __restrict__ senders,
                   const int*   __restrict__ receivers,
                   float*       __restrict__ out,
                   int ntime)
{
    __shared__ float sbias1[NEDGES_LOC * BSTRIDE];        // stride-33: conflict-free
    __shared__ float s_lm[NPLANETS];
    __shared__ float s_invm[NPLANETS];
    __shared__ int   s_snd[NEDGES_LOC];
    __shared__ int   s_rcv[NEDGES_LOC];
    __shared__ int   s_glist[NPLANETS][9];                // +(le+1) recv, -(le+1) send
    __shared__ __align__(16) float4 s_e[EDGES_PB];        // per-edge cartesian force

    const int tid = threadIdx.x;

    // ---- cooperative setup ----
    if (tid < NEDGES_LOC) { s_snd[tid] = senders[tid]; s_rcv[tid] = receivers[tid]; }
    if (tid < NPLANETS) {
        float v = fminf(fmaxf(logm[tid], -12.0f), 12.0f);
        s_lm[tid]   = v;
        s_invm[tid] = expf(-v);
    }
    __syncthreads();

    if (tid < NPLANETS) {
        int cnt = 0;
        for (int le = 0; le < NEDGES_LOC; le++) {
            if (s_rcv[le] == tid) s_glist[tid][cnt++] =  (le + 1);
            else if (s_snd[le] == tid) s_glist[tid][cnt++] = -(le + 1);
        }
    }
    // bias1 table: b1 + lm[r]*W1row3 + lm[s]*W1row4  (global reads, one-off)
    for (int i = tid; i < NEDGES_LOC * HID; i += THREADS) {
        int le = i >> 5;
        int j  = i & 31;
        sbias1[le * BSTRIDE + j] = b1[j] + s_lm[s_rcv[le]] * W1[3 * HID + j]
                                         + s_lm[s_snd[le]] * W1[4 * HID + j];
    }
    __syncthreads();

    // ---- per-edge compute ----
    const int  t_local = tid / NEDGES_LOC;
    const int  le      = tid - t_local * NEDGES_LOC;
    const long t_glob  = (long)blockIdx.x * NT_PER_BLOCK + t_local;

    if (tid < EDGES_PB && t_glob < (long)ntime) {
        long g = (long)blockIdx.x * EDGES_PB + tid;
        float x = D_V[g * 3 + 0];
        float y = D_V[g * 3 + 1];
        float z = D_V[g * 3 + 2];

        float r2 = fmaf(x, x, fmaf(y, y, z * z));
        float r  = sqrtf(r2);
        float ct = fminf(fmaxf(__fdividef(z, r), -1.0f), 1.0f);
        float th = acos_f(ct);
        float ph = atan2_f(y, x);

        const float* bias = sbias1 + le * BSTRIDE;

        // fused layer1+layer2: scalar layer-1 activation, packed f32x2
        // rank-1 update of acc (16 x 64-bit pairs covering 32 outputs).
        ull acc[16];
#pragma unroll
        for (int q = 0; q < 8; q++) {
            ulonglong2 v = cb2p[q];
            acc[2*q] = v.x; acc[2*q+1] = v.y;
        }

#pragma unroll
        for (int k = 0; k < HID; k++) {
            float pre = fmaf(r,  cW1[k],
                        fmaf(th, cW1[HID + k],
                        fmaf(ph, cW1[2 * HID + k], bias[k])));
            ull hk = pk2(tanha(pre));
#pragma unroll
            for (int q = 0; q < 8; q++) {
                ulonglong2 w = cW2p[k * 8 + q];
                acc[2*q]   = fma2(hk, w.x, acc[2*q]);
                acc[2*q+1] = fma2(hk, w.y, acc[2*q+1]);
            }
        }

        // layer 3: e = tanh(acc) @ W3 + b3
        float e0 = cb3[0], e1 = cb3[1], e2 = cb3[2];
#pragma unroll
        for (int q = 0; q < 16; q++) {
            float lo, hi;
            upk(acc[q], lo, hi);
            float ha = tanha(lo), hb = tanha(hi);
            int k = 2 * q;
            e0 = fmaf(ha, cW3[k * 3 + 0], e0);
            e1 = fmaf(ha, cW3[k * 3 + 1], e1);
            e2 = fmaf(ha, cW3[k * 3 + 2], e2);
            e0 = fmaf(hb, cW3[k * 3 + 3], e0);
            e1 = fmaf(hb, cW3[k * 3 + 4], e1);
            e2 = fmaf(hb, cW3[k * 3 + 5], e2);
        }

        // sph -> cart
        float st, ctq, sp, cp;
        __sincosf(e1, &st, &ctq);
        __sincosf(e2, &sp, &cp);
        float rs = e0 * st;
        s_e[tid] = make_float4(rs * cp, rs * sp, e0 * ctq, 0.0f);
    }
    __syncthreads();

    // ---- gather-based scatter: 210 threads = 7 t * 10 planets * 3 comps ----
    if (tid < NT_PER_BLOCK * NPLANETS * 3) {
        int tl  = tid / (NPLANETS * 3);
        int rem = tid - tl * (NPLANETS * 3);
        int p   = rem / 3;
        int c   = rem - p * 3;
        long t  = (long)blockIdx.x * NT_PER_BLOCK + tl;
        if (t < (long)ntime) {
            const float* eb = (const float*)(s_e + tl * NEDGES_LOC);
            float sum = 0.0f;
#pragma unroll
            for (int k = 0; k < 9; k++) {
                int gidx = s_glist[p][k];
                int lle  = (gidx > 0 ? gidx : -gidx) - 1;
                float v  = eb[lle * 4 + c];
                sum += (gidx > 0) ? v : -v;
            }
            out[t * (NPLANETS * 3) + rem] = sum * s_invm[p];
        }
    }
}

extern "C" void kernel_launch(void* const* d_in, const int* in_sizes, int n_in,
                              void* d_out, int out_size)
{
    const float* D_V       = (const float*)d_in[0];
    const float* logm      = (const float*)d_in[1];
    const float* W1        = (const float*)d_in[2];
    const float* b1        = (const float*)d_in[3];
    const float* W2        = (const float*)d_in[4];
    const float* b2        = (const float*)d_in[5];
    const float* W3        = (const float*)d_in[6];
    const float* b3        = (const float*)d_in[7];
    const int*   senders   = (const int*)d_in[8];
    const int*   receivers = (const int*)d_in[9];
    float*       out       = (float*)d_out;

    // Stage weights into __constant__ (graph-capturable async D2D copies).
    cudaMemcpyToSymbolAsync(cW1,  W1, 3 * HID * sizeof(float), 0, cudaMemcpyDeviceToDevice);
    cudaMemcpyToSymbolAsync(cW2p, W2, HID * HID * sizeof(float), 0, cudaMemcpyDeviceToDevice);
    cudaMemcpyToSymbolAsync(cb2p, b2, HID * sizeof(float), 0, cudaMemcpyDeviceToDevice);
    cudaMemcpyToSymbolAsync(cW3,  W3, HID * 3 * sizeof(float), 0, cudaMemcpyDeviceToDevice);
    cudaMemcpyToSymbolAsync(cb3,  b3, 3 * sizeof(float), 0, cudaMemcpyDeviceToDevice);

    int nedges = in_sizes[8];                  // 45
    int ntime  = in_sizes[0] / (3 * nedges);   // 100000

    int grid = (ntime + NT_PER_BLOCK - 1) / NT_PER_BLOCK;
    learnforces_kernel<<<grid, THREADS>>>(D_V, logm, W1, b1,
                                          senders, receivers, out, ntime);
}